// round 1
// baseline (speedup 1.0000x reference)
#include <cuda_runtime.h>
#include <cstdint>

#define N_ATOMS 200000
#define OUT_F 256
#define IN_F 256
#define BOND_F 6
#define KTOT 518           // 256 self + 256 nbr-atom + 6 nbr-bond
#define KPAD 520
#define TILE_M 32
#define NTH 256
#define KC 8
#define NCHUNK (KPAD / KC) // 65
#define EPSV 1e-5f

__device__ double g_sum[OUT_F];
__device__ double g_sumsq[OUT_F];
__device__ __align__(16) float g_scale[OUT_F];
__device__ __align__(16) float g_shift[OUT_F];

struct Params {
    const float* atom;
    const float* bond;
    const int* an[5];
    const int* bn[5];
    const float* Wself;
    const float* bias;
    const float* Wdeg[5];
    float* out;
};

__global__ void zero_stats_kernel() {
    g_sum[threadIdx.x] = 0.0;
    g_sumsq[threadIdx.x] = 0.0;
}

// Fetch a float4 of the virtually-stacked W = [W_self(256 rows); W_deg(262 rows); zero pad]
__device__ __forceinline__ float4 fetch_w(const float* Wself, const float* Wd,
                                          int k, int c4) {
    if (k < IN_F)  return ((const float4*)Wself)[k * 64 + c4];
    if (k < KTOT)  return ((const float4*)Wd)[(k - IN_F) * 64 + c4];
    return make_float4(0.f, 0.f, 0.f, 0.f);
}

__global__ __launch_bounds__(NTH) void fused_gcl_kernel(Params p) {
    extern __shared__ float sm[];
    float* X    = sm;                       // [TILE_M][KPAD]
    float* Wt   = X + TILE_M * KPAD;        // [2][KC][OUT_F] double-buffered
    float* ssum = Wt + 2 * KC * OUT_F;      // [OUT_F]
    float* ssq  = ssum + OUT_F;             // [OUT_F]
    int*   sidx = (int*)(ssq + OUT_F);      // [160] atom idx, [160] bond idx

    const int tid = threadIdx.x;
    const int r0  = blockIdx.x * TILE_M;

    // degree group (tile never crosses a boundary; all boundaries % 32 == 0)
    int g, segStart;
    if      (r0 >= 180000) { g = 4; segStart = 180000; }
    else if (r0 >= 140000) { g = 3; segStart = 140000; }
    else if (r0 >= 80000)  { g = 2; segStart = 80000;  }
    else if (r0 >= 20000)  { g = 1; segStart = 20000;  }
    else                   { g = 0; segStart = 0;      }
    const int deg    = g + 1;
    const int local0 = r0 - segStart;
    const int*   an = p.an[g];
    const int*   bn = p.bn[g];
    const float* Wd = p.Wdeg[g];

    ssum[tid] = 0.f;
    ssq[tid]  = 0.f;

    // stage neighbor index lists
    const int nIdx = TILE_M * deg;
    for (int i = tid; i < nIdx; i += NTH) {
        sidx[i]       = an[(size_t)local0 * deg + i];
        sidx[160 + i] = bn[(size_t)local0 * deg + i];
    }
    __syncthreads();

    // stage X: self features [0,256), summed nbr atom features [256,512),
    // summed nbr bond features [512,518), pad [518,520)
    const float4* atom4 = (const float4*)p.atom;
    for (int i = tid; i < TILE_M * 64; i += NTH) {
        int row = i >> 6, c4 = i & 63;
        ((float4*)(X + row * KPAD))[c4] = atom4[(size_t)(r0 + row) * 64 + c4];
    }
    for (int i = tid; i < TILE_M * 64; i += NTH) {
        int row = i >> 6, c4 = i & 63;
        float4 a = make_float4(0.f, 0.f, 0.f, 0.f);
        for (int j = 0; j < deg; j++) {
            float4 v = atom4[(size_t)sidx[row * deg + j] * 64 + c4];
            a.x += v.x; a.y += v.y; a.z += v.z; a.w += v.w;
        }
        ((float4*)(X + row * KPAD + IN_F))[c4] = a;
    }
    for (int i = tid; i < TILE_M * 8; i += NTH) {
        int row = i >> 3, c = i & 7;
        float v = 0.f;
        if (c < BOND_F) {
            for (int j = 0; j < deg; j++)
                v += p.bond[(size_t)sidx[160 + row * deg + j] * BOND_F + c];
        }
        X[row * KPAD + 2 * IN_F + c] = v;   // cols 512..519 (518,519 stay 0)
    }

    // ---- GEMM: acc[4 rows][8 cols], cols = {4*tn+j} and {128+4*tn+j} ----
    const int tm = tid >> 5, tn = tid & 31;
    float acc[4][8];
#pragma unroll
    for (int i = 0; i < 4; i++)
#pragma unroll
        for (int j = 0; j < 8; j++) acc[i][j] = 0.f;

    const int kl0 = tid >> 6,          cc0 = tid & 63;         // rows 0..3 of chunk
    const int kl1 = (tid + 256) >> 6,  cc1 = tid & 63;         // rows 4..7

    float4 ra = fetch_w(p.Wself, Wd, kl0, cc0);
    float4 rb = fetch_w(p.Wself, Wd, kl1, cc1);
    __syncthreads();               // X staging complete
    ((float4*)Wt)[tid]       = ra;
    ((float4*)Wt)[tid + 256] = rb;
    __syncthreads();

    const float* Xb0 = X + (tm * 4 + 0) * KPAD;
    const float* Xb1 = X + (tm * 4 + 1) * KPAD;
    const float* Xb2 = X + (tm * 4 + 2) * KPAD;
    const float* Xb3 = X + (tm * 4 + 3) * KPAD;

#pragma unroll 1
    for (int c = 0; c < NCHUNK; c++) {
        float4 na, nb;
        const bool more = (c + 1 < NCHUNK);
        if (more) {
            na = fetch_w(p.Wself, Wd, (c + 1) * KC + kl0, cc0);
            nb = fetch_w(p.Wself, Wd, (c + 1) * KC + kl1, cc1);
        }
        const float* Wb = Wt + (c & 1) * (KC * OUT_F);
#pragma unroll
        for (int k = 0; k < KC; k++) {
            float4 w0 = *(const float4*)(Wb + k * OUT_F + 4 * tn);
            float4 w1 = *(const float4*)(Wb + k * OUT_F + 128 + 4 * tn);
            const int kk = c * KC + k;
            float x0 = Xb0[kk], x1 = Xb1[kk], x2 = Xb2[kk], x3 = Xb3[kk];
            acc[0][0] += x0 * w0.x; acc[0][1] += x0 * w0.y;
            acc[0][2] += x0 * w0.z; acc[0][3] += x0 * w0.w;
            acc[0][4] += x0 * w1.x; acc[0][5] += x0 * w1.y;
            acc[0][6] += x0 * w1.z; acc[0][7] += x0 * w1.w;
            acc[1][0] += x1 * w0.x; acc[1][1] += x1 * w0.y;
            acc[1][2] += x1 * w0.z; acc[1][3] += x1 * w0.w;
            acc[1][4] += x1 * w1.x; acc[1][5] += x1 * w1.y;
            acc[1][6] += x1 * w1.z; acc[1][7] += x1 * w1.w;
            acc[2][0] += x2 * w0.x; acc[2][1] += x2 * w0.y;
            acc[2][2] += x2 * w0.z; acc[2][3] += x2 * w0.w;
            acc[2][4] += x2 * w1.x; acc[2][5] += x2 * w1.y;
            acc[2][6] += x2 * w1.z; acc[2][7] += x2 * w1.w;
            acc[3][0] += x3 * w0.x; acc[3][1] += x3 * w0.y;
            acc[3][2] += x3 * w0.z; acc[3][3] += x3 * w0.w;
            acc[3][4] += x3 * w1.x; acc[3][5] += x3 * w1.y;
            acc[3][6] += x3 * w1.z; acc[3][7] += x3 * w1.w;
        }
        __syncthreads();
        if (more) {
            float* Wn = Wt + ((c + 1) & 1) * (KC * OUT_F);
            ((float4*)Wn)[tid]       = na;
            ((float4*)Wn)[tid + 256] = nb;
        }
        __syncthreads();
    }

    // ---- epilogue: +bias, ReLU, store, per-column sum/sumsq ----
    float4 b0 = ((const float4*)p.bias)[tn];
    float4 b1 = ((const float4*)p.bias)[32 + tn];
    float lsum[8], lsq[8];
#pragma unroll
    for (int j = 0; j < 8; j++) { lsum[j] = 0.f; lsq[j] = 0.f; }

#pragma unroll
    for (int i = 0; i < 4; i++) {
        const int r = r0 + tm * 4 + i;
        float v0 = fmaxf(acc[i][0] + b0.x, 0.f);
        float v1 = fmaxf(acc[i][1] + b0.y, 0.f);
        float v2 = fmaxf(acc[i][2] + b0.z, 0.f);
        float v3 = fmaxf(acc[i][3] + b0.w, 0.f);
        float v4 = fmaxf(acc[i][4] + b1.x, 0.f);
        float v5 = fmaxf(acc[i][5] + b1.y, 0.f);
        float v6 = fmaxf(acc[i][6] + b1.z, 0.f);
        float v7 = fmaxf(acc[i][7] + b1.w, 0.f);
        *(float4*)(p.out + (size_t)r * OUT_F + 4 * tn)       = make_float4(v0, v1, v2, v3);
        *(float4*)(p.out + (size_t)r * OUT_F + 128 + 4 * tn) = make_float4(v4, v5, v6, v7);
        lsum[0] += v0; lsq[0] += v0 * v0;
        lsum[1] += v1; lsq[1] += v1 * v1;
        lsum[2] += v2; lsq[2] += v2 * v2;
        lsum[3] += v3; lsq[3] += v3 * v3;
        lsum[4] += v4; lsq[4] += v4 * v4;
        lsum[5] += v5; lsq[5] += v5 * v5;
        lsum[6] += v6; lsq[6] += v6 * v6;
        lsum[7] += v7; lsq[7] += v7 * v7;
    }
#pragma unroll
    for (int j = 0; j < 8; j++) {
        const int col = (j < 4) ? (4 * tn + j) : (128 + 4 * tn + (j - 4));
        atomicAdd(&ssum[col], lsum[j]);
        atomicAdd(&ssq[col],  lsq[j]);
    }
    __syncthreads();
    atomicAdd(&g_sum[tid],   (double)ssum[tid]);
    atomicAdd(&g_sumsq[tid], (double)ssq[tid]);
}

__global__ void finalize_stats_kernel(const float* __restrict__ bnw,
                                      const float* __restrict__ bnb) {
    const int c = threadIdx.x;
    double mean = g_sum[c] / (double)N_ATOMS;
    double var  = g_sumsq[c] / (double)N_ATOMS - mean * mean;
    float s = bnw[c] * rsqrtf((float)var + EPSV);
    g_scale[c] = s;
    g_shift[c] = bnb[c] - (float)mean * s;
}

__global__ void apply_bn_kernel(float* __restrict__ out) {
    const size_t i = (size_t)blockIdx.x * blockDim.x + threadIdx.x; // float4 idx
    float4 v = ((float4*)out)[i];
    const int c4 = (int)(i & 63);
    float4 s = ((const float4*)g_scale)[c4];
    float4 t = ((const float4*)g_shift)[c4];
    v.x = v.x * s.x + t.x;
    v.y = v.y * s.y + t.y;
    v.z = v.z * s.z + t.z;
    v.w = v.w * s.w + t.w;
    ((float4*)out)[i] = v;
}

extern "C" void kernel_launch(void* const* d_in, const int* in_sizes, int n_in,
                              void* d_out, int out_size) {
    Params P;
    P.atom = (const float*)d_in[0];
    P.bond = (const float*)d_in[1];
    // Two plausible orderings of the 10 neighbor arrays:
    //  interleaved (setup_inputs dict order): an1,bn1,an2,bn2,... -> sizes[2]==sizes[3]
    //  grouped (reference signature order):   an1..an5, bn1..bn5  -> sizes[2]!=sizes[3]
    const bool interleaved = (in_sizes[2] == in_sizes[3]);
    for (int d = 0; d < 5; d++) {
        if (interleaved) {
            P.an[d] = (const int*)d_in[2 + 2 * d];
            P.bn[d] = (const int*)d_in[3 + 2 * d];
        } else {
            P.an[d] = (const int*)d_in[2 + d];
            P.bn[d] = (const int*)d_in[7 + d];
        }
    }
    P.Wself = (const float*)d_in[12];
    P.bias  = (const float*)d_in[13];
    for (int d = 0; d < 5; d++) P.Wdeg[d] = (const float*)d_in[14 + d];
    const float* bnw = (const float*)d_in[19];
    const float* bnb = (const float*)d_in[20];
    P.out = (float*)d_out;

    const int SMEM = (TILE_M * KPAD + 2 * KC * OUT_F + 2 * OUT_F) * 4 + 320 * 4;
    cudaFuncSetAttribute(fused_gcl_kernel,
                         cudaFuncAttributeMaxDynamicSharedMemorySize, SMEM);

    zero_stats_kernel<<<1, OUT_F>>>();
    fused_gcl_kernel<<<N_ATOMS / TILE_M, NTH, SMEM>>>(P);
    finalize_stats_kernel<<<1, OUT_F>>>(bnw, bnb);
    apply_bn_kernel<<<(N_ATOMS * (OUT_F / 4)) / 256, 256>>>((float*)d_out);
}